// round 13
// baseline (speedup 1.0000x reference)
#include <cuda_runtime.h>
#include <cuda_bf16.h>

// ---------------------------------------------------------------------------
// point_transformer, Round 13
//   - stage 4 back to FFMA2 (fp32 Wa1 regs) -> tensor pipe (rt=16/SMSP for
//     legacy mma.sync!) relieved by 33%, idle fma pipe absorbs it
//   - B3 -> __syncwarp (stages 2-3 are warp-column-local)
//   - prologue float4-vectorized
// ---------------------------------------------------------------------------
#define NMAX 50000
#define MPAD 50048     // 391 * 128
#define HH   16

typedef unsigned long long ull;

__device__ float g_qkv[NMAX * 768];     // [n][0:256)=q [256:512)=k [512:768)=v
__device__ int   g_inds[NMAX * HH];
__device__ float g_bcat[768];
__device__ __nv_bfloat16 g_ahi[MPAD * 256];
__device__ __nv_bfloat16 g_alo[MPAD * 256];
__device__ __nv_bfloat16 g_whiT[768 * 256];    // Wcat^T: [n][k]
__device__ __nv_bfloat16 g_wloT[768 * 256];
__device__ __nv_bfloat16 g_wd2hiT[256 * 64];   // Wd2^T: [c][d]
__device__ __nv_bfloat16 g_wd2loT[256 * 64];

static __device__ __forceinline__ float lrelu(float x) {
    return fmaxf(x, 0.1f * x);
}
static __device__ __forceinline__ ull ffma2(ull a, ull b, ull c) {
    ull d;
    asm("fma.rn.f32x2 %0, %1, %2, %3;" : "=l"(d) : "l"(a), "l"(b), "l"(c));
    return d;
}
static __device__ __forceinline__ ull addf2(ull a, ull b) {
    ull d;
    asm("add.rn.f32x2 %0, %1, %2;" : "=l"(d) : "l"(a), "l"(b));
    return d;
}
static __device__ __forceinline__ ull pack2(float x, float y) {
    ull r;
    asm("mov.b64 %0, {%1, %2};" : "=l"(r) : "f"(x), "f"(y));
    return r;
}
static __device__ __forceinline__ float2 unpack2(ull v) {
    float2 f;
    asm("mov.b64 {%0, %1}, %2;" : "=f"(f.x), "=f"(f.y) : "l"(v));
    return f;
}
static __device__ __forceinline__ void mma_bf16(float* d, const unsigned* a,
                                                const unsigned* b) {
    asm volatile(
        "mma.sync.aligned.m16n8k16.row.col.f32.bf16.bf16.f32 "
        "{%0,%1,%2,%3}, {%4,%5,%6,%7}, {%8,%9}, {%0,%1,%2,%3};"
        : "+f"(d[0]), "+f"(d[1]), "+f"(d[2]), "+f"(d[3])
        : "r"(a[0]), "r"(a[1]), "r"(a[2]), "r"(a[3]), "r"(b[0]), "r"(b[1]));
}
static __device__ __forceinline__ ull pack4bf_hi(float a, float b, float c, float d) {
    unsigned short u0 = __bfloat16_as_ushort(__float2bfloat16(a));
    unsigned short u1 = __bfloat16_as_ushort(__float2bfloat16(b));
    unsigned short u2 = __bfloat16_as_ushort(__float2bfloat16(c));
    unsigned short u3 = __bfloat16_as_ushort(__float2bfloat16(d));
    return (ull)u0 | ((ull)u1 << 16) | ((ull)u2 << 32) | ((ull)u3 << 48);
}
static __device__ __forceinline__ unsigned smem_u32(const void* p) {
    unsigned a;
    asm("{ .reg .u64 t; cvta.to.shared.u64 t, %1; cvt.u32.u64 %0, t; }"
        : "=r"(a) : "l"(p));
    return a;
}
static __device__ __forceinline__ void cp16(unsigned smaddr, const void* g) {
    asm volatile("cp.async.cg.shared.global [%0], [%1], 16;"
                 :: "r"(smaddr), "l"(g) : "memory");
}
#define CP_COMMIT() asm volatile("cp.async.commit_group;" ::: "memory")
#define CP_WAIT(n)  asm volatile("cp.async.wait_group %0;" :: "n"(n) : "memory")

// --------------------------- fused prologue (float4-vectorized) -------------
__global__ void pt_prologue(const unsigned* __restrict__ nb, int total_idx,
                            const float* __restrict__ A, int M,
                            const float* __restrict__ Wq, const float* __restrict__ bq,
                            const float* __restrict__ Wk, const float* __restrict__ bk,
                            const float* __restrict__ Wv, const float* __restrict__ bv,
                            const float* __restrict__ Wd2) {
    const int b = blockIdx.x;
    const int t = threadIdx.x;
    const int i = b * 256 + t;

    // A -> bf16 hi/lo, 4 elements per thread (grid covers MPAD*256/4 threads)
    {
        const int i4  = i * 4;
        const int row = i4 >> 8;
        float4 av = (row < M) ? *(const float4*)&A[i4]
                              : make_float4(0.f, 0.f, 0.f, 0.f);
        float h0 = __bfloat162float(__float2bfloat16(av.x));
        float h1 = __bfloat162float(__float2bfloat16(av.y));
        float h2 = __bfloat162float(__float2bfloat16(av.z));
        float h3 = __bfloat162float(__float2bfloat16(av.w));
        *(ull*)&g_ahi[i4] = pack4bf_hi(h0, h1, h2, h3);
        *(ull*)&g_alo[i4] = pack4bf_hi(av.x - h0, av.y - h1, av.z - h2, av.w - h3);
    }
    if (i < 768 * 256) {
        int n = i >> 8, k = i & 255;
        float w;
        if      (n < 256) w = Wq[k * 256 + n];
        else if (n < 512) w = Wk[k * 256 + (n - 256)];
        else              w = Wv[k * 256 + (n - 512)];
        __nv_bfloat16 hi = __float2bfloat16(w);
        g_whiT[i] = hi;
        g_wloT[i] = __float2bfloat16(w - __bfloat162float(hi));
    }
    if (i < 256 * 64) {
        int c = i >> 6, d = i & 63;
        float w = Wd2[d * 256 + c];
        __nv_bfloat16 hi = __float2bfloat16(w);
        g_wd2hiT[i] = hi;
        g_wd2loT[i] = __float2bfloat16(w - __bfloat162float(hi));
    }
    if (i < 768) {
        g_bcat[i] = (i < 256) ? bq[i] : (i < 512 ? bk[i - 256] : bv[i - 512]);
    }
    if (b * 256 < total_idx) {
        __shared__ int flag;
        if (t == 0) flag = 0;
        __syncthreads();
        const int half = total_idx >> 1;
        int stride = half >> 8;
        if (stride < 1) stride = 1;
        int s = (t * stride) % half;
        if (nb[2 * s + 1] != 0u) flag = 1;
        __syncthreads();
        if (i < total_idx) {
            if (flag) g_inds[i] = ((const int*)nb)[i];
            else      g_inds[i] = (int)(((const long long*)nb)[i]);
        }
    }
}

// --------------------------- mma.sync QKV GEMM (cp.async x4 stages) ---------
#define SK2     24
#define TILE2   (128 * SK2 * 2)          // 6144 bytes per tile
#define STAGE2  (4 * TILE2)              // 24576: Ahi|Alo|Bhi|Blo
#define NSTAGE  4
#define GEMM_SMEM (NSTAGE * STAGE2)      // 98304

extern __shared__ char sm_raw[];

__global__ void __launch_bounds__(256, 2)
pt_qkv_gemm_mma(int M) {
    char* gsm = sm_raw;
    const unsigned sbase = smem_u32(gsm);

    const int t    = threadIdx.x;
    const int warp = t >> 5;
    const int lane = t & 31;
    const int gid  = lane >> 2;
    const int tq   = lane & 3;
    const int m0 = blockIdx.x * 128;
    const int n0 = blockIdx.y * 128;
    const int mw = (warp & 1) * 64;
    const int nw = (warp >> 1) * 32;

    const int crow = t >> 1;
    const int ckq  = t & 1;

    float acc[4][4][4];
    #pragma unroll
    for (int mt = 0; mt < 4; mt++)
        #pragma unroll
        for (int nt = 0; nt < 4; nt++)
            #pragma unroll
            for (int r = 0; r < 4; r++) acc[mt][nt][r] = 0.f;

    auto issue = [&](int kc, int buf) {
        const int k0 = kc * 16;
        const unsigned dst = sbase + buf * STAGE2 + crow * (SK2 * 2) + ckq * 16;
        const int asrc = (m0 + crow) * 256 + k0 + ckq * 8;
        const int bsrc = (n0 + crow) * 256 + k0 + ckq * 8;
        cp16(dst + 0 * TILE2, &g_ahi[asrc]);
        cp16(dst + 1 * TILE2, &g_alo[asrc]);
        cp16(dst + 2 * TILE2, &g_whiT[bsrc]);
        cp16(dst + 3 * TILE2, &g_wloT[bsrc]);
        CP_COMMIT();
    };

    issue(0, 0);
    issue(1, 1);
    issue(2, 2);

    for (int kc = 0; kc < 16; kc++) {
        CP_WAIT(2);
        __syncthreads();

        char* base = gsm + (kc & 3) * STAGE2;
        const __nv_bfloat16* smAhi = (const __nv_bfloat16*)(base);
        const __nv_bfloat16* smAlo = (const __nv_bfloat16*)(base + 1 * TILE2);
        const __nv_bfloat16* smBhi = (const __nv_bfloat16*)(base + 2 * TILE2);
        const __nv_bfloat16* smBlo = (const __nv_bfloat16*)(base + 3 * TILE2);

        const int kk = tq * 2;
        unsigned bh[4][2], bl[4][2];
        #pragma unroll
        for (int nt = 0; nt < 4; nt++) {
            const int nr = nw + nt * 8 + gid;
            bh[nt][0] = *(const unsigned*)&smBhi[nr * SK2 + kk];
            bh[nt][1] = *(const unsigned*)&smBhi[nr * SK2 + kk + 8];
            bl[nt][0] = *(const unsigned*)&smBlo[nr * SK2 + kk];
            bl[nt][1] = *(const unsigned*)&smBlo[nr * SK2 + kk + 8];
        }
        #pragma unroll
        for (int mt = 0; mt < 4; mt++) {
            const int mr = mw + mt * 16 + gid;
            unsigned ah[4], al[4];
            ah[0] = *(const unsigned*)&smAhi[ mr      * SK2 + kk];
            ah[1] = *(const unsigned*)&smAhi[(mr + 8) * SK2 + kk];
            ah[2] = *(const unsigned*)&smAhi[ mr      * SK2 + kk + 8];
            ah[3] = *(const unsigned*)&smAhi[(mr + 8) * SK2 + kk + 8];
            al[0] = *(const unsigned*)&smAlo[ mr      * SK2 + kk];
            al[1] = *(const unsigned*)&smAlo[(mr + 8) * SK2 + kk];
            al[2] = *(const unsigned*)&smAlo[ mr      * SK2 + kk + 8];
            al[3] = *(const unsigned*)&smAlo[(mr + 8) * SK2 + kk + 8];
            #pragma unroll
            for (int nt = 0; nt < 4; nt++) {
                mma_bf16(acc[mt][nt], ah, bh[nt]);
                mma_bf16(acc[mt][nt], ah, bl[nt]);
                mma_bf16(acc[mt][nt], al, bh[nt]);
            }
        }

        if (kc + 3 < 16) issue(kc + 3, (kc + 3) & 3);
    }

    #pragma unroll
    for (int mt = 0; mt < 4; mt++) {
        const int r0 = m0 + mw + mt * 16 + gid;
        const int r1 = r0 + 8;
        #pragma unroll
        for (int nt = 0; nt < 4; nt++) {
            const int col = n0 + nw + nt * 8 + tq * 2;
            const float b0 = g_bcat[col], b1 = g_bcat[col + 1];
            if (r0 < M) {
                float2 o = make_float2(acc[mt][nt][0] + b0, acc[mt][nt][1] + b1);
                *(float2*)&g_qkv[r0 * 768 + col] = o;
            }
            if (r1 < M) {
                float2 o = make_float2(acc[mt][nt][2] + b0, acc[mt][nt][3] + b1);
                *(float2*)&g_qkv[r1 * 768 + col] = o;
            }
        }
    }
}

// --------------------------- fused attention --------------------------------
// 768 threads = three 256-thread halves (named barriers 1/2/3).
// h-pair convention: (h=hp, h=hp+8). Stage 2->3 is warp-local (syncwarp).
#define OFF_WD2H  0        // bf16 [256][72] -> 9216 floats
#define OFF_WD2L  9216
#define OFF_WA2   18432    // [32][32]
#define OFF_WD1   19456
#define OFF_BD1   19648
#define OFF_BD2   19712
#define OFF_BA1   19968
#define OFF_BA2   20000
#define WEIGHT_FLOATS 20032

#define PP_HIDH   0        // bf16 [16][72] = 576 floats
#define PP_HIDL   576      // bf16 [16][72]
#define PP_A2     1152     // ull [8][258] = 4128 floats (a, packed f32 h-pairs)
#define PP_GP     5280     // OVERLAY: geom2 ull[8][260] (4160) / partu ull[8][8][34] (4352)
#define PP_L1     9632     // [16][34]
#define PP_L2     10176    // [16][34]
#define PP_ATTN   10720    // ull [8][34] = 544 floats
#define PP_INDS   11264    // 16 ints
#define PP_QPT    11280    // 3 floats + pad
#define PP_FLOATS 11284

#define SMEM_FLOATS (WEIGHT_FLOATS + 3 * PP_FLOATS)
#define SMEM_BYTES  (SMEM_FLOATS * 4)

#define HBAR(id) asm volatile("bar.sync %0, 256;" :: "r"(id) : "memory")

__global__ void __launch_bounds__(768, 1)
pt_fused_attn(const float* __restrict__ q_pts,
              const float* __restrict__ s_pts,
              const float* __restrict__ Wd1, const float* __restrict__ bd1,
              const float* __restrict__ bd2,
              const float* __restrict__ Wa1, const float* __restrict__ ba1,
              const float* __restrict__ Wa2, const float* __restrict__ ba2,
              float* __restrict__ out, int N) {
    float* sm = (float*)sm_raw;
    __nv_bfloat16* Wd2THs = (__nv_bfloat16*)(sm + OFF_WD2H);  // [256 c][72 d]
    __nv_bfloat16* Wd2TLs = (__nv_bfloat16*)(sm + OFF_WD2L);
    float* Wa2s = sm + OFF_WA2;
    float* Wd1s = sm + OFF_WD1;
    float* bd1s = sm + OFF_BD1;
    float* bd2s = sm + OFF_BD2;
    float* ba1s = sm + OFF_BA1;
    float* ba2s = sm + OFF_BA2;

    const int t   = threadIdx.x;
    const int pid = t >> 8;         // 0,1,2
    const int tt  = t & 255;
    const int ww  = (t >> 5) & 7;   // warp in half: owns c-slice [32ww, 32ww+32)
    const int l   = t & 31;
    const int gid = l >> 2;
    const int tq  = l & 3;
    const int bid = pid + 1;

    float* pp     = sm + WEIGHT_FLOATS + pid * PP_FLOATS;
    __nv_bfloat16* hidH = (__nv_bfloat16*)(pp + PP_HIDH);   // [16 h][72 d]
    __nv_bfloat16* hidL = (__nv_bfloat16*)(pp + PP_HIDL);
    ull*   a2u    = (ull*)(pp + PP_A2);     // [8 hp][258 c] packed f32 pairs
    ull*   geom2  = (ull*)(pp + PP_GP);     // [8 hp][260 c]   (overlay)
    ull*   partu  = (ull*)(pp + PP_GP);     // [(ww*8+hp)*34+m] (overlay)
    float* l1s    = pp + PP_L1;
    float* l2s    = pp + PP_L2;
    ull*   attn2  = (ull*)(pp + PP_ATTN);
    int*   inds_s = (int*)(pp + PP_INDS);
    float* qptf   = pp + PP_QPT;

    // persistent Wa1 register cache (fp32): wreg[j] = Wa1[32*ww + j][l]
    float wreg[32];
    #pragma unroll
    for (int j = 0; j < 32; j++)
        wreg[j] = Wa1[(ww * 32 + j) * 32 + l];

    // stage 0: weights -> shared (all 768 threads)
    for (int i = t; i < 256 * 16; i += 768) {
        int n = i >> 4, k4 = (i & 15) * 4;
        *(ull*)&Wd2THs[n * 72 + k4] = ((const ull*)g_wd2hiT)[i];
        *(ull*)&Wd2TLs[n * 72 + k4] = ((const ull*)g_wd2loT)[i];
    }
    for (int i = t; i < 1024; i += 768) Wa2s[i] = Wa2[i];
    if (t < 192) Wd1s[t] = Wd1[t];
    if (t < 64)  bd1s[t] = bd1[t];
    if (t < 256) bd2s[t] = bd2[t];
    if (t < 32) { ba1s[t] = ba1[t]; ba2s[t] = ba2[t]; }
    __syncthreads();

    // ---- pipeline preamble: first point's indices + gather prefetch ----
    int n3 = blockIdx.x;
    {
        int nreq = n3 * 3 + pid;
        int n0p  = (nreq < N) ? nreq : (N - 1);
        if (tt < 16) inds_s[tt] = g_inds[n0p * 16 + tt];
        if (tt < 3)  qptf[tt]   = q_pts[n0p * 3 + tt];
    }
    HBAR(bid);

    float qf, sx, sy, sz, nk[16];
    qf = g_qkv[inds_s[0] * 768 + tt];
    {
        const int j1 = inds_s[tt >> 4];
        sx = s_pts[j1 * 3 + 0];
        sy = s_pts[j1 * 3 + 1];
        sz = s_pts[j1 * 3 + 2];
    }
    #pragma unroll
    for (int h = 0; h < 16; h++)
        nk[h] = g_qkv[inds_s[h] * 768 + 256 + tt];

    while (true) {
        const int nreq = n3 * 3 + pid;
        const int n = (nreq < N) ? nreq : (N - 1);
        const bool do_store = (nreq < N);

        // stage 1: hidden = lrelu(rel @ Wd1 + bd1), bf16 hi/lo (stride 72)
        {
            const int d0 = (tt & 15) << 2;
            const int h  = tt >> 4;
            const float rx = sx - qptf[0];
            const float ry = sy - qptf[1];
            const float rz = sz - qptf[2];
            float vv[4], vh[4], vl[4];
            #pragma unroll
            for (int i = 0; i < 4; i++) {
                const int d = d0 + i;
                float v = rx * Wd1s[d] + ry * Wd1s[64 + d] + rz * Wd1s[128 + d] + bd1s[d];
                vv[i] = lrelu(v);
                vh[i] = __bfloat162float(__float2bfloat16(vv[i]));
                vl[i] = vv[i] - vh[i];
            }
            *(ull*)&hidH[h * 72 + d0] = pack4bf_hi(vh[0], vh[1], vh[2], vh[3]);
            *(ull*)&hidL[h * 72 + d0] = pack4bf_hi(vl[0], vl[1], vl[2], vl[3]);
        }
        HBAR(bid);                                          // B2

        // stage 2: geom = hid @ Wd2 via mma (hi/lo split); D rows (gid, gid+8)
        {
            float acc[4][4];
            #pragma unroll
            for (int nt = 0; nt < 4; nt++)
                #pragma unroll
                for (int r = 0; r < 4; r++) acc[nt][r] = 0.f;

            #pragma unroll
            for (int kc = 0; kc < 4; kc++) {
                const int k0 = kc * 16;
                unsigned ah[4], al[4];
                ah[0] = *(const unsigned*)&hidH[ gid      * 72 + k0 + tq * 2];
                ah[1] = *(const unsigned*)&hidH[(gid + 8) * 72 + k0 + tq * 2];
                ah[2] = *(const unsigned*)&hidH[ gid      * 72 + k0 + 8 + tq * 2];
                ah[3] = *(const unsigned*)&hidH[(gid + 8) * 72 + k0 + 8 + tq * 2];
                al[0] = *(const unsigned*)&hidL[ gid      * 72 + k0 + tq * 2];
                al[1] = *(const unsigned*)&hidL[(gid + 8) * 72 + k0 + tq * 2];
                al[2] = *(const unsigned*)&hidL[ gid      * 72 + k0 + 8 + tq * 2];
                al[3] = *(const unsigned*)&hidL[(gid + 8) * 72 + k0 + 8 + tq * 2];
                #pragma unroll
                for (int nt = 0; nt < 4; nt++) {
                    const int nr = ww * 32 + nt * 8 + gid;
                    unsigned bh[2], bl[2];
                    bh[0] = *(const unsigned*)&Wd2THs[nr * 72 + k0 + tq * 2];
                    bh[1] = *(const unsigned*)&Wd2THs[nr * 72 + k0 + 8 + tq * 2];
                    bl[0] = *(const unsigned*)&Wd2TLs[nr * 72 + k0 + tq * 2];
                    bl[1] = *(const unsigned*)&Wd2TLs[nr * 72 + k0 + 8 + tq * 2];
                    mma_bf16(acc[nt], ah, bh);
                    mma_bf16(acc[nt], ah, bl);
                    mma_bf16(acc[nt], al, bh);
                }
            }
            #pragma unroll
            for (int nt = 0; nt < 4; nt++) {
                const int c0 = ww * 32 + nt * 8 + tq * 2;
                const float b0 = bd2s[c0], b1 = bd2s[c0 + 1];
                geom2[gid * 260 + c0    ] = pack2(acc[nt][0] + b0, acc[nt][2] + b0);
                geom2[gid * 260 + c0 + 1] = pack2(acc[nt][1] + b1, acc[nt][3] + b1);
            }
        }
        __syncwarp();     // stage 2 -> 3 is warp-column-local

        // stage 3: a = lrelu(qf - nk - geom), packed f32 h-pairs (warp-local)
        ull g[8];
        #pragma unroll
        for (int hp = 0; hp < 8; hp++) {
            g[hp] = geom2[hp * 260 + tt];
            const float2 gp = unpack2(g[hp]);
            const float ax = lrelu(qf - nk[hp]     - gp.x);
            const float ay = lrelu(qf - nk[hp + 8] - gp.y);
            a2u[hp * 258 + tt] = pack2(ax, ay);
        }
        HBAR(bid);        // B4: all geom2 reads done before partu overlay writes

        // stage 4: logits1 partials via FFMA2 (Wa1 in regs, broadcast LDS)
        {
            ull acc[8];
            #pragma unroll
            for (int hp = 0; hp < 8; hp++) acc[hp] = 0ull;
            const int cbase = ww * 32;
            #pragma unroll
            for (int jv = 0; jv < 16; jv++) {
                const ull w0 = pack2(wreg[2*jv],     wreg[2*jv]);
                const ull w1 = pack2(wreg[2*jv + 1], wreg[2*jv + 1]);
                #pragma unroll
                for (int hp = 0; hp < 8; hp++) {
                    ulonglong2 av = *(const ulonglong2*)&a2u[hp * 258 + cbase + 2*jv];
                    acc[hp] = ffma2(av.x, w0, acc[hp]);
                    acc[hp] = ffma2(av.y, w1, acc[hp]);
                }
            }
            #pragma unroll
            for (int hp = 0; hp < 8; hp++)
                partu[(ww * 8 + hp) * 34 + l] = acc[hp];
        }

        // early LDGs: next point's indices/qpt into regs + current nv prefetch
        const int n3n = n3 + gridDim.x;
        int   nxt_ind = 0;
        float nxt_qp  = 0.f;
        {
            int nreqn = n3n * 3 + pid;
            int nn = (nreqn < N) ? nreqn : (N - 1);
            if (tt < 16) nxt_ind = g_inds[nn * 16 + tt];
            if (tt < 3)  nxt_qp  = q_pts[nn * 3 + tt];
        }
        float nv[16];
        #pragma unroll
        for (int h = 0; h < 16; h++)
            nv[h] = g_qkv[inds_s[h] * 768 + 512 + tt];
        HBAR(bid);                                          // B5

        // commit pipeline advance (inds_s free after B5)
        n3 = n3n;
        const bool more = (n3 * 3 < N);
        if (tt < 16) inds_s[tt] = nxt_ind;
        if (tt < 3)  qptf[tt]   = nxt_qp;

        // stage 4b+5 merged (warp-local)
        {
            const float b = ba1s[l];
            ull s = pack2(b, b);
            #pragma unroll
            for (int w8 = 0; w8 < 8; w8++)
                s = addf2(s, partu[(w8 * 8 + ww) * 34 + l]);
            float2 v = unpack2(s);
            l1s[ ww      * 34 + l] = lrelu(v.x);
            l1s[(ww + 8) * 34 + l] = lrelu(v.y);
            __syncwarp();

            const int h  = ww + 8 * (l >> 4);
            const int m0 = (l & 15) * 2;
            ull acc01 = pack2(ba2s[m0], ba2s[m0 + 1]);
            const float* lrow = l1s + h * 34;
            #pragma unroll
            for (int jj = 0; jj < 32; jj++) {
                const float lv = lrow[jj];
                ull w2 = *(const ull*)(Wa2s + jj * 32 + m0);
                acc01 = ffma2(pack2(lv, lv), w2, acc01);
            }
            float2 r = unpack2(acc01);
            l2s[h * 34 + m0    ] = r.x;
            l2s[h * 34 + m0 + 1] = r.y;
        }
        HBAR(bid);                                          // B6

        // stage 6: softmax over h; attn pairs (hp, hp+8)
        if (tt < 32) {
            float vals[16];
            float mx = -3.4e38f;
            #pragma unroll
            for (int h = 0; h < 16; h++) {
                vals[h] = l2s[h * 34 + tt];
                mx = fmaxf(mx, vals[h]);
            }
            float s = 0.f;
            #pragma unroll
            for (int h = 0; h < 16; h++) {
                vals[h] = __expf(vals[h] - mx);
                s += vals[h];
            }
            const float inv = 1.f / s;
            #pragma unroll
            for (int hp = 0; hp < 8; hp++)
                attn2[hp * 34 + tt] = pack2(vals[hp] * inv, vals[hp + 8] * inv);
        }
        HBAR(bid);                                          // B7

        // stage 7: out + next point's gather prefetch
        {
            const int mg = tt >> 3;
            ull acc2p = 0ull;
            #pragma unroll
            for (int hp = 0; hp < 8; hp++) {
                const float2 gp = unpack2(g[hp]);
                ull vm = pack2(nv[hp] - gp.x, nv[hp + 8] - gp.y);
                acc2p = ffma2(vm, attn2[hp * 34 + mg], acc2p);
            }
            float2 r = unpack2(acc2p);
            if (do_store) out[n * 256 + tt] = r.x + r.y;
        }
        if (!more) break;

        qf = g_qkv[inds_s[0] * 768 + tt];
        {
            const int j1 = inds_s[tt >> 4];
            sx = s_pts[j1 * 3 + 0];
            sy = s_pts[j1 * 3 + 1];
            sz = s_pts[j1 * 3 + 2];
        }
        #pragma unroll
        for (int h = 0; h < 16; h++)
            nk[h] = g_qkv[inds_s[h] * 768 + 256 + tt];
    }
}

// --------------------------- launch ------------------------------------------
extern "C" void kernel_launch(void* const* d_in, const int* in_sizes, int n_in,
                              void* d_out, int out_size) {
    const float* q_pts   = (const float*)d_in[0];
    const float* s_pts   = (const float*)d_in[1];
    const float* s_feats = (const float*)d_in[2];
    const void*  nb_inds = d_in[3];
    const float* Wq = (const float*)d_in[4];
    const float* bq = (const float*)d_in[5];
    const float* Wk = (const float*)d_in[6];
    const float* bk = (const float*)d_in[7];
    const float* Wv = (const float*)d_in[8];
    const float* bv = (const float*)d_in[9];
    const float* Wd1 = (const float*)d_in[10];
    const float* bd1 = (const float*)d_in[11];
    const float* Wd2 = (const float*)d_in[12];
    const float* bd2 = (const float*)d_in[13];
    const float* Wa1 = (const float*)d_in[14];
    const float* ba1 = (const float*)d_in[15];
    const float* Wa2 = (const float*)d_in[16];
    const float* ba2 = (const float*)d_in[17];
    float* out = (float*)d_out;

    const int N = in_sizes[0] / 3;

    cudaFuncSetAttribute(pt_fused_attn,
                         cudaFuncAttributeMaxDynamicSharedMemorySize, SMEM_BYTES);
    cudaFuncSetAttribute(pt_qkv_gemm_mma,
                         cudaFuncAttributeMaxDynamicSharedMemorySize, GEMM_SMEM);

    pt_prologue<<<MPAD / 4, 256>>>((const unsigned*)nb_inds, N * HH,
                                   s_feats, N,
                                   Wq, bq, Wk, bk, Wv, bv, Wd2);

    dim3 ggrid((N + 127) / 128, 6);
    pt_qkv_gemm_mma<<<ggrid, 256, GEMM_SMEM>>>(N);

    int fgrid = 148;
    if (fgrid * 3 > N) fgrid = (N + 2) / 3;
    pt_fused_attn<<<fgrid, 768, SMEM_BYTES>>>(q_pts, s_pts,
                                              Wd1, bd1, bd2,
                                              Wa1, ba1, Wa2, ba2,
                                              out, N);
}

// round 14
// speedup vs baseline: 1.2515x; 1.2515x over previous
#include <cuda_runtime.h>
#include <cuda_bf16.h>

// ---------------------------------------------------------------------------
// point_transformer, Round 14  (R12 fused+GEMM  +  R13 vectorized prologue)
//   - R13's stage-4 FFMA2 switch REVERTED (register spills at 768 thr)
//   - prologue float4-vectorized (verified -20us), Wa1 prepack restored
// ---------------------------------------------------------------------------
#define NMAX 50000
#define MPAD 50048     // 391 * 128
#define HH   16

typedef unsigned long long ull;

__device__ float g_qkv[NMAX * 768];     // [n][0:256)=q [256:512)=k [512:768)=v
__device__ int   g_inds[NMAX * HH];
__device__ float g_bcat[768];
__device__ __nv_bfloat16 g_ahi[MPAD * 256];
__device__ __nv_bfloat16 g_alo[MPAD * 256];
__device__ __nv_bfloat16 g_whiT[768 * 256];    // Wcat^T: [n][k]
__device__ __nv_bfloat16 g_wloT[768 * 256];
__device__ __nv_bfloat16 g_wd2hiT[256 * 64];   // Wd2^T: [c][d]
__device__ __nv_bfloat16 g_wd2loT[256 * 64];
__device__ __nv_bfloat16 g_wa1hiT[32 * 256];   // Wa1^T: [m][c]
__device__ __nv_bfloat16 g_wa1loT[32 * 256];

static __device__ __forceinline__ float lrelu(float x) {
    return fmaxf(x, 0.1f * x);
}
static __device__ __forceinline__ ull ffma2(ull a, ull b, ull c) {
    ull d;
    asm("fma.rn.f32x2 %0, %1, %2, %3;" : "=l"(d) : "l"(a), "l"(b), "l"(c));
    return d;
}
static __device__ __forceinline__ ull addf2(ull a, ull b) {
    ull d;
    asm("add.rn.f32x2 %0, %1, %2;" : "=l"(d) : "l"(a), "l"(b));
    return d;
}
static __device__ __forceinline__ ull pack2(float x, float y) {
    ull r;
    asm("mov.b64 %0, {%1, %2};" : "=l"(r) : "f"(x), "f"(y));
    return r;
}
static __device__ __forceinline__ float2 unpack2(ull v) {
    float2 f;
    asm("mov.b64 {%0, %1}, %2;" : "=f"(f.x), "=f"(f.y) : "l"(v));
    return f;
}
static __device__ __forceinline__ void mma_bf16(float* d, const unsigned* a,
                                                const unsigned* b) {
    asm volatile(
        "mma.sync.aligned.m16n8k16.row.col.f32.bf16.bf16.f32 "
        "{%0,%1,%2,%3}, {%4,%5,%6,%7}, {%8,%9}, {%0,%1,%2,%3};"
        : "+f"(d[0]), "+f"(d[1]), "+f"(d[2]), "+f"(d[3])
        : "r"(a[0]), "r"(a[1]), "r"(a[2]), "r"(a[3]), "r"(b[0]), "r"(b[1]));
}
static __device__ __forceinline__ ull pack4bf_hi(float a, float b, float c, float d) {
    unsigned short u0 = __bfloat16_as_ushort(__float2bfloat16(a));
    unsigned short u1 = __bfloat16_as_ushort(__float2bfloat16(b));
    unsigned short u2 = __bfloat16_as_ushort(__float2bfloat16(c));
    unsigned short u3 = __bfloat16_as_ushort(__float2bfloat16(d));
    return (ull)u0 | ((ull)u1 << 16) | ((ull)u2 << 32) | ((ull)u3 << 48);
}
static __device__ __forceinline__ unsigned smem_u32(const void* p) {
    unsigned a;
    asm("{ .reg .u64 t; cvta.to.shared.u64 t, %1; cvt.u32.u64 %0, t; }"
        : "=r"(a) : "l"(p));
    return a;
}
static __device__ __forceinline__ void cp16(unsigned smaddr, const void* g) {
    asm volatile("cp.async.cg.shared.global [%0], [%1], 16;"
                 :: "r"(smaddr), "l"(g) : "memory");
}
#define CP_COMMIT() asm volatile("cp.async.commit_group;" ::: "memory")
#define CP_WAIT(n)  asm volatile("cp.async.wait_group %0;" :: "n"(n) : "memory")

// --------------------------- fused prologue (float4-vectorized) -------------
__global__ void pt_prologue(const unsigned* __restrict__ nb, int total_idx,
                            const float* __restrict__ A, int M,
                            const float* __restrict__ Wq, const float* __restrict__ bq,
                            const float* __restrict__ Wk, const float* __restrict__ bk,
                            const float* __restrict__ Wv, const float* __restrict__ bv,
                            const float* __restrict__ Wd2, const float* __restrict__ Wa1) {
    const int b = blockIdx.x;
    const int t = threadIdx.x;
    const int i = b * 256 + t;

    // A -> bf16 hi/lo, 4 elements per thread (grid = MPAD/4 blocks)
    {
        const int i4  = i * 4;
        const int row = i4 >> 8;
        float4 av = (row < M) ? *(const float4*)&A[i4]
                              : make_float4(0.f, 0.f, 0.f, 0.f);
        float h0 = __bfloat162float(__float2bfloat16(av.x));
        float h1 = __bfloat162float(__float2bfloat16(av.y));
        float h2 = __bfloat162float(__float2bfloat16(av.z));
        float h3 = __bfloat162float(__float2bfloat16(av.w));
        *(ull*)&g_ahi[i4] = pack4bf_hi(h0, h1, h2, h3);
        *(ull*)&g_alo[i4] = pack4bf_hi(av.x - h0, av.y - h1, av.z - h2, av.w - h3);
    }
    if (i < 768 * 256) {
        int n = i >> 8, k = i & 255;
        float w;
        if      (n < 256) w = Wq[k * 256 + n];
        else if (n < 512) w = Wk[k * 256 + (n - 256)];
        else              w = Wv[k * 256 + (n - 512)];
        __nv_bfloat16 hi = __float2bfloat16(w);
        g_whiT[i] = hi;
        g_wloT[i] = __float2bfloat16(w - __bfloat162float(hi));
    }
    if (i < 256 * 64) {
        int c = i >> 6, d = i & 63;
        float w = Wd2[d * 256 + c];
        __nv_bfloat16 hi = __float2bfloat16(w);
        g_wd2hiT[i] = hi;
        g_wd2loT[i] = __float2bfloat16(w - __bfloat162float(hi));
    }
    if (i < 32 * 256) {
        int m = i >> 8, k = i & 255;
        float w = Wa1[k * 32 + m];
        __nv_bfloat16 hi = __float2bfloat16(w);
        g_wa1hiT[i] = hi;
        g_wa1loT[i] = __float2bfloat16(w - __bfloat162float(hi));
    }
    if (i < 768) {
        g_bcat[i] = (i < 256) ? bq[i] : (i < 512 ? bk[i - 256] : bv[i - 512]);
    }
    if (b * 256 < total_idx) {
        __shared__ int flag;
        if (t == 0) flag = 0;
        __syncthreads();
        const int half = total_idx >> 1;
        int stride = half >> 8;
        if (stride < 1) stride = 1;
        int s = (t * stride) % half;
        if (nb[2 * s + 1] != 0u) flag = 1;
        __syncthreads();
        if (i < total_idx) {
            if (flag) g_inds[i] = ((const int*)nb)[i];
            else      g_inds[i] = (int)(((const long long*)nb)[i]);
        }
    }
}

// --------------------------- mma.sync QKV GEMM (cp.async x4 stages) ---------
#define SK2     24
#define TILE2   (128 * SK2 * 2)          // 6144 bytes per tile
#define STAGE2  (4 * TILE2)              // 24576: Ahi|Alo|Bhi|Blo
#define NSTAGE  4
#define GEMM_SMEM (NSTAGE * STAGE2)      // 98304

extern __shared__ char sm_raw[];

__global__ void __launch_bounds__(256, 2)
pt_qkv_gemm_mma(int M) {
    char* gsm = sm_raw;
    const unsigned sbase = smem_u32(gsm);

    const int t    = threadIdx.x;
    const int warp = t >> 5;
    const int lane = t & 31;
    const int gid  = lane >> 2;
    const int tq   = lane & 3;
    const int m0 = blockIdx.x * 128;
    const int n0 = blockIdx.y * 128;
    const int mw = (warp & 1) * 64;
    const int nw = (warp >> 1) * 32;

    const int crow = t >> 1;
    const int ckq  = t & 1;

    float acc[4][4][4];
    #pragma unroll
    for (int mt = 0; mt < 4; mt++)
        #pragma unroll
        for (int nt = 0; nt < 4; nt++)
            #pragma unroll
            for (int r = 0; r < 4; r++) acc[mt][nt][r] = 0.f;

    auto issue = [&](int kc, int buf) {
        const int k0 = kc * 16;
        const unsigned dst = sbase + buf * STAGE2 + crow * (SK2 * 2) + ckq * 16;
        const int asrc = (m0 + crow) * 256 + k0 + ckq * 8;
        const int bsrc = (n0 + crow) * 256 + k0 + ckq * 8;
        cp16(dst + 0 * TILE2, &g_ahi[asrc]);
        cp16(dst + 1 * TILE2, &g_alo[asrc]);
        cp16(dst + 2 * TILE2, &g_whiT[bsrc]);
        cp16(dst + 3 * TILE2, &g_wloT[bsrc]);
        CP_COMMIT();
    };

    issue(0, 0);
    issue(1, 1);
    issue(2, 2);

    for (int kc = 0; kc < 16; kc++) {
        CP_WAIT(2);
        __syncthreads();

        char* base = gsm + (kc & 3) * STAGE2;
        const __nv_bfloat16* smAhi = (const __nv_bfloat16*)(base);
        const __nv_bfloat16* smAlo = (const __nv_bfloat16*)(base + 1 * TILE2);
        const __nv_bfloat16* smBhi = (const __nv_bfloat16*)(base + 2 * TILE2);
        const __nv_bfloat16* smBlo = (const __nv_bfloat16*)(base + 3 * TILE2);

        const int kk = tq * 2;
        unsigned bh[4][2], bl[4][2];
        #pragma unroll
        for (int nt = 0; nt < 4; nt++) {
            const int nr = nw + nt * 8 + gid;
            bh[nt][0] = *(const unsigned*)&smBhi[nr * SK2 + kk];
            bh[nt][1] = *(const unsigned*)&smBhi[nr * SK2 + kk + 8];
            bl[nt][0] = *(const unsigned*)&smBlo[nr * SK2 + kk];
            bl[nt][1] = *(const unsigned*)&smBlo[nr * SK2 + kk + 8];
        }
        #pragma unroll
        for (int mt = 0; mt < 4; mt++) {
            const int mr = mw + mt * 16 + gid;
            unsigned ah[4], al[4];
            ah[0] = *(const unsigned*)&smAhi[ mr      * SK2 + kk];
            ah[1] = *(const unsigned*)&smAhi[(mr + 8) * SK2 + kk];
            ah[2] = *(const unsigned*)&smAhi[ mr      * SK2 + kk + 8];
            ah[3] = *(const unsigned*)&smAhi[(mr + 8) * SK2 + kk + 8];
            al[0] = *(const unsigned*)&smAlo[ mr      * SK2 + kk];
            al[1] = *(const unsigned*)&smAlo[(mr + 8) * SK2 + kk];
            al[2] = *(const unsigned*)&smAlo[ mr      * SK2 + kk + 8];
            al[3] = *(const unsigned*)&smAlo[(mr + 8) * SK2 + kk + 8];
            #pragma unroll
            for (int nt = 0; nt < 4; nt++) {
                mma_bf16(acc[mt][nt], ah, bh[nt]);
                mma_bf16(acc[mt][nt], ah, bl[nt]);
                mma_bf16(acc[mt][nt], al, bh[nt]);
            }
        }

        if (kc + 3 < 16) issue(kc + 3, (kc + 3) & 3);
    }

    #pragma unroll
    for (int mt = 0; mt < 4; mt++) {
        const int r0 = m0 + mw + mt * 16 + gid;
        const int r1 = r0 + 8;
        #pragma unroll
        for (int nt = 0; nt < 4; nt++) {
            const int col = n0 + nw + nt * 8 + tq * 2;
            const float b0 = g_bcat[col], b1 = g_bcat[col + 1];
            if (r0 < M) {
                float2 o = make_float2(acc[mt][nt][0] + b0, acc[mt][nt][1] + b1);
                *(float2*)&g_qkv[r0 * 768 + col] = o;
            }
            if (r1 < M) {
                float2 o = make_float2(acc[mt][nt][2] + b0, acc[mt][nt][3] + b1);
                *(float2*)&g_qkv[r1 * 768 + col] = o;
            }
        }
    }
}

// --------------------------- fused attention --------------------------------
// 768 threads = three independent 256-thread halves (named barriers 1/2/3).
// h-pair convention: pair hp = (h=hp, h=hp+8). Cross-point software pipeline.
#define OFF_WD2H  0        // bf16 [256][72] -> 9216 floats
#define OFF_WD2L  9216
#define OFF_WA1L  18432    // bf16 [32][264] -> 4224 floats
#define OFF_WA2   22656    // [32][32]
#define OFF_WD1   23680
#define OFF_BD1   23872
#define OFF_BD2   23936
#define OFF_BA1   24192
#define OFF_BA2   24224
#define WEIGHT_FLOATS 24256

#define PP_AH     0        // bf16 [16][264] = 2112 floats
#define PP_AL     2112     // bf16 [16][264]
#define PP_GP     4224     // OVERLAY: geom2 ull[8][260] (4160) / partu ull[8][8][34] (4352)
#define PP_L1     8576     // [16][34]
#define PP_L2     9120     // [16][34]
#define PP_ATTN   9664     // ull [8][34] = 544 floats
#define PP_INDS   10208    // 16 ints
#define PP_QPT    10224    // 3 floats + pad
#define PP_FLOATS 10228

#define SMEM_FLOATS (WEIGHT_FLOATS + 3 * PP_FLOATS)
#define SMEM_BYTES  (SMEM_FLOATS * 4)

#define HBAR(id) asm volatile("bar.sync %0, 256;" :: "r"(id) : "memory")

__global__ void __launch_bounds__(768, 1)
pt_fused_attn(const float* __restrict__ q_pts,
              const float* __restrict__ s_pts,
              const float* __restrict__ Wd1, const float* __restrict__ bd1,
              const float* __restrict__ bd2,
              const float* __restrict__ ba1,
              const float* __restrict__ Wa2, const float* __restrict__ ba2,
              float* __restrict__ out, int N) {
    float* sm = (float*)sm_raw;
    __nv_bfloat16* Wd2THs = (__nv_bfloat16*)(sm + OFF_WD2H);  // [256 c][72 d]
    __nv_bfloat16* Wd2TLs = (__nv_bfloat16*)(sm + OFF_WD2L);
    __nv_bfloat16* Wa1Ls  = (__nv_bfloat16*)(sm + OFF_WA1L);  // [32 m][264 c]
    float* Wa2s = sm + OFF_WA2;
    float* Wd1s = sm + OFF_WD1;
    float* bd1s = sm + OFF_BD1;
    float* bd2s = sm + OFF_BD2;
    float* ba1s = sm + OFF_BA1;
    float* ba2s = sm + OFF_BA2;

    const int t   = threadIdx.x;
    const int pid = t >> 8;         // 0,1,2
    const int tt  = t & 255;
    const int ww  = (t >> 5) & 7;   // warp in half: owns c-slice [32ww, 32ww+32)
    const int l   = t & 31;
    const int gid = l >> 2;
    const int tq  = l & 3;
    const int bid = pid + 1;

    float* pp     = sm + WEIGHT_FLOATS + pid * PP_FLOATS;
    __nv_bfloat16* aH = (__nv_bfloat16*)(pp + PP_AH);   // [16 h][264 c]
    __nv_bfloat16* aL = (__nv_bfloat16*)(pp + PP_AL);
    ull*   geom2  = (ull*)(pp + PP_GP);     // [8 hp][260 c]   (overlay)
    ull*   partu  = (ull*)(pp + PP_GP);     // [(ww*8+hp)*34+m] (overlay)
    float* l1s    = pp + PP_L1;
    float* l2s    = pp + PP_L2;
    ull*   attn2  = (ull*)(pp + PP_ATTN);
    int*   inds_s = (int*)(pp + PP_INDS);
    float* qptf   = pp + PP_QPT;

    // persistent Wa1 HI B-fragments in registers; LO stays in smem
    unsigned wbh[4][2][2];
    #pragma unroll
    for (int nt = 0; nt < 4; nt++)
        #pragma unroll
        for (int s = 0; s < 2; s++) {
            const int m  = nt * 8 + gid;
            const int k0 = ww * 32 + s * 16 + tq * 2;
            wbh[nt][s][0] = *(const unsigned*)&g_wa1hiT[m * 256 + k0];
            wbh[nt][s][1] = *(const unsigned*)&g_wa1hiT[m * 256 + k0 + 8];
        }

    // stage 0: weights -> shared (all 768 threads)
    for (int i = t; i < 256 * 16; i += 768) {
        int n = i >> 4, k4 = (i & 15) * 4;
        *(ull*)&Wd2THs[n * 72 + k4] = ((const ull*)g_wd2hiT)[i];
        *(ull*)&Wd2TLs[n * 72 + k4] = ((const ull*)g_wd2loT)[i];
    }
    for (int i = t; i < 2048; i += 768) {
        int m = i >> 6, u = i & 63;
        *(ull*)&Wa1Ls[m * 264 + u * 4] = ((const ull*)g_wa1loT)[i];
    }
    for (int i = t; i < 1024; i += 768) Wa2s[i] = Wa2[i];
    if (t < 192) Wd1s[t] = Wd1[t];
    if (t < 64)  bd1s[t] = bd1[t];
    if (t < 256) bd2s[t] = bd2[t];
    if (t < 32) { ba1s[t] = ba1[t]; ba2s[t] = ba2[t]; }
    __syncthreads();

    // ---- pipeline preamble: first point's indices + gather prefetch ----
    int n3 = blockIdx.x;
    {
        int nreq = n3 * 3 + pid;
        int n0p  = (nreq < N) ? nreq : (N - 1);
        if (tt < 16) inds_s[tt] = g_inds[n0p * 16 + tt];
        if (tt < 3)  qptf[tt]   = q_pts[n0p * 3 + tt];
    }
    HBAR(bid);

    float qf, sx, sy, sz, nk[16];
    qf = g_qkv[inds_s[0] * 768 + tt];
    {
        const int j1 = inds_s[tt >> 4];
        sx = s_pts[j1 * 3 + 0];
        sy = s_pts[j1 * 3 + 1];
        sz = s_pts[j1 * 3 + 2];
    }
    #pragma unroll
    for (int h = 0; h < 16; h++)
        nk[h] = g_qkv[inds_s[h] * 768 + 256 + tt];

    while (true) {
        const int nreq = n3 * 3 + pid;
        const int n = (nreq < N) ? nreq : (N - 1);
        const bool do_store = (nreq < N);

        // stage 1: hidden = lrelu(rel @ Wd1 + bd1), bf16 hi/lo (stride 72)
        {
            const int d0 = (tt & 15) << 2;
            const int h  = tt >> 4;
            const float rx = sx - qptf[0];
            const float ry = sy - qptf[1];
            const float rz = sz - qptf[2];
            float vv[4], vh[4], vl[4];
            #pragma unroll
            for (int i = 0; i < 4; i++) {
                const int d = d0 + i;
                float v = rx * Wd1s[d] + ry * Wd1s[64 + d] + rz * Wd1s[128 + d] + bd1s[d];
                vv[i] = lrelu(v);
                vh[i] = __bfloat162float(__float2bfloat16(vv[i]));
                vl[i] = vv[i] - vh[i];
            }
            *(ull*)&aH[h * 72 + d0] = pack4bf_hi(vh[0], vh[1], vh[2], vh[3]);
            *(ull*)&aL[h * 72 + d0] = pack4bf_hi(vl[0], vl[1], vl[2], vl[3]);
        }
        HBAR(bid);                                          // B2

        // stage 2: geom = hid @ Wd2 via mma (hi/lo split); D rows (gid, gid+8)
        {
            float acc[4][4];
            #pragma unroll
            for (int nt = 0; nt < 4; nt++)
                #pragma unroll
                for (int r = 0; r < 4; r++) acc[nt][r] = 0.f;

            #pragma unroll
            for (int kc = 0; kc < 4; kc++) {
                const int k0 = kc * 16;
                unsigned ah[4], al[4];
                ah[0] = *(const unsigned*)&aH[ gid      * 72 + k0 + tq * 2];
                ah[1] = *(const unsigned*)&aH[(gid + 8) * 72 + k0 + tq * 2];
                ah[2] = *(const unsigned*)&aH[ gid      * 72 + k0 + 8 + tq * 2];
                ah[3] = *(const unsigned*)&aH[(gid + 8) * 72 + k0 + 8 + tq * 2];
                al[0] = *(const unsigned*)&aL[ gid      * 72 + k0 + tq * 2];
                al[1] = *(const unsigned*)&aL[(gid + 8) * 72 + k0 + tq * 2];
                al[2] = *(const unsigned*)&aL[ gid      * 72 + k0 + 8 + tq * 2];
                al[3] = *(const unsigned*)&aL[(gid + 8) * 72 + k0 + 8 + tq * 2];
                #pragma unroll
                for (int nt = 0; nt < 4; nt++) {
                    const int nr = ww * 32 + nt * 8 + gid;
                    unsigned bh[2], bl[2];
                    bh[0] = *(const unsigned*)&Wd2THs[nr * 72 + k0 + tq * 2];
                    bh[1] = *(const unsigned*)&Wd2THs[nr * 72 + k0 + 8 + tq * 2];
                    bl[0] = *(const unsigned*)&Wd2TLs[nr * 72 + k0 + tq * 2];
                    bl[1] = *(const unsigned*)&Wd2TLs[nr * 72 + k0 + 8 + tq * 2];
                    mma_bf16(acc[nt], ah, bh);
                    mma_bf16(acc[nt], ah, bl);
                    mma_bf16(acc[nt], al, bh);
                }
            }
            #pragma unroll
            for (int nt = 0; nt < 4; nt++) {
                const int c0 = ww * 32 + nt * 8 + tq * 2;
                const float b0 = bd2s[c0], b1 = bd2s[c0 + 1];
                geom2[gid * 260 + c0    ] = pack2(acc[nt][0] + b0, acc[nt][2] + b0);
                geom2[gid * 260 + c0 + 1] = pack2(acc[nt][1] + b1, acc[nt][3] + b1);
            }
        }
        HBAR(bid);                                          // B3

        // stage 3: a = lrelu(qf - nk - geom); store bf16 hi/lo [16][264]
        ull g[8];
        #pragma unroll
        for (int hp = 0; hp < 8; hp++) {
            g[hp] = geom2[hp * 260 + tt];
            const float2 gp = unpack2(g[hp]);
            const float ax = lrelu(qf - nk[hp]     - gp.x);
            const float ay = lrelu(qf - nk[hp + 8] - gp.y);
            __nv_bfloat16 hx = __float2bfloat16(ax);
            __nv_bfloat16 hy = __float2bfloat16(ay);
            aH[ hp      * 264 + tt] = hx;
            aH[(hp + 8) * 264 + tt] = hy;
            aL[ hp      * 264 + tt] = __float2bfloat16(ax - __bfloat162float(hx));
            aL[(hp + 8) * 264 + tt] = __float2bfloat16(ay - __bfloat162float(hy));
        }
        HBAR(bid);                                          // B4

        // stage 4: logits1 partials via mma (Wa1 hi in regs, lo in smem)
        {
            float acc[4][4];
            #pragma unroll
            for (int nt = 0; nt < 4; nt++)
                #pragma unroll
                for (int r = 0; r < 4; r++) acc[nt][r] = 0.f;

            #pragma unroll
            for (int s = 0; s < 2; s++) {
                const int kk = ww * 32 + s * 16 + tq * 2;
                unsigned ah[4], al[4];
                ah[0] = *(const unsigned*)&aH[ gid      * 264 + kk];
                ah[1] = *(const unsigned*)&aH[(gid + 8) * 264 + kk];
                ah[2] = *(const unsigned*)&aH[ gid      * 264 + kk + 8];
                ah[3] = *(const unsigned*)&aH[(gid + 8) * 264 + kk + 8];
                al[0] = *(const unsigned*)&aL[ gid      * 264 + kk];
                al[1] = *(const unsigned*)&aL[(gid + 8) * 264 + kk];
                al[2] = *(const unsigned*)&aL[ gid      * 264 + kk + 8];
                al[3] = *(const unsigned*)&aL[(gid + 8) * 264 + kk + 8];
                #pragma unroll
                for (int nt = 0; nt < 4; nt++) {
                    const int m = nt * 8 + gid;
                    unsigned bl[2];
                    bl[0] = *(const unsigned*)&Wa1Ls[m * 264 + ww * 32 + s * 16 + tq * 2];
                    bl[1] = *(const unsigned*)&Wa1Ls[m * 264 + ww * 32 + s * 16 + tq * 2 + 8];
                    mma_bf16(acc[nt], ah, wbh[nt][s]);
                    mma_bf16(acc[nt], ah, bl);
                    mma_bf16(acc[nt], al, wbh[nt][s]);
                }
            }
            #pragma unroll
            for (int nt = 0; nt < 4; nt++) {
                const int m = nt * 8 + tq * 2;
                ulonglong2 v;
                v.x = pack2(acc[nt][0], acc[nt][2]);
                v.y = pack2(acc[nt][1], acc[nt][3]);
                *(ulonglong2*)&partu[(ww * 8 + gid) * 34 + m] = v;
            }
        }

        // early LDGs: next point's indices/qpt into REGISTERS (pre-B5:
        // latency hidden under stage-4 MMAs) + current point's nv prefetch
        const int n3n = n3 + gridDim.x;
        int   nxt_ind = 0;
        float nxt_qp  = 0.f;
        {
            int nreqn = n3n * 3 + pid;
            int nn = (nreqn < N) ? nreqn : (N - 1);
            if (tt < 16) nxt_ind = g_inds[nn * 16 + tt];
            if (tt < 3)  nxt_qp  = q_pts[nn * 3 + tt];
        }
        float nv[16];
        #pragma unroll
        for (int h = 0; h < 16; h++)
            nv[h] = g_qkv[inds_s[h] * 768 + 512 + tt];
        HBAR(bid);                                          // B5

        // commit pipeline advance (inds_s free after B5)
        n3 = n3n;
        const bool more = (n3 * 3 < N);    // uniform across CTA
        if (tt < 16) inds_s[tt] = nxt_ind;
        if (tt < 3)  qptf[tt]   = nxt_qp;

        // stage 4b+5 merged (warp-local): warp w reduces l1 rows (w, w+8),
        // then computes l2 rows after __syncwarp.
        {
            const float b = ba1s[l];
            ull s = pack2(b, b);
            #pragma unroll
            for (int w8 = 0; w8 < 8; w8++)
                s = addf2(s, partu[(w8 * 8 + ww) * 34 + l]);
            float2 v = unpack2(s);
            l1s[ ww      * 34 + l] = lrelu(v.x);
            l1s[(ww + 8) * 34 + l] = lrelu(v.y);
            __syncwarp();

            const int h  = ww + 8 * (l >> 4);
            const int m0 = (l & 15) * 2;
            ull acc01 = pack2(ba2s[m0], ba2s[m0 + 1]);
            const float* lrow = l1s + h * 34;
            #pragma unroll
            for (int jj = 0; jj < 32; jj++) {
                const float lv = lrow[jj];
                ull w2 = *(const ull*)(Wa2s + jj * 32 + m0);
                acc01 = ffma2(pack2(lv, lv), w2, acc01);
            }
            float2 r = unpack2(acc01);
            l2s[h * 34 + m0    ] = r.x;
            l2s[h * 34 + m0 + 1] = r.y;
        }
        HBAR(bid);                                          // B6

        // stage 6: softmax over h; attn pairs (hp, hp+8)
        if (tt < 32) {
            float vals[16];
            float mx = -3.4e38f;
            #pragma unroll
            for (int h = 0; h < 16; h++) {
                vals[h] = l2s[h * 34 + tt];
                mx = fmaxf(mx, vals[h]);
            }
            float s = 0.f;
            #pragma unroll
            for (int h = 0; h < 16; h++) {
                vals[h] = __expf(vals[h] - mx);
                s += vals[h];
            }
            const float inv = 1.f / s;
            #pragma unroll
            for (int hp = 0; hp < 8; hp++)
                attn2[hp * 34 + tt] = pack2(vals[hp] * inv, vals[hp + 8] * inv);
        }
        HBAR(bid);                                          // B7

        // stage 7: out + NEXT point's gather prefetch (new inds_s visible)
        {
            const int mg = tt >> 3;
            ull acc2p = 0ull;
            #pragma unroll
            for (int hp = 0; hp < 8; hp++) {
                const float2 gp = unpack2(g[hp]);
                ull vm = pack2(nv[hp] - gp.x, nv[hp + 8] - gp.y);
                acc2p = ffma2(vm, attn2[hp * 34 + mg], acc2p);
            }
            float2 r = unpack2(acc2p);
            if (do_store) out[n * 256 + tt] = r.x + r.y;
        }
        if (!more) break;

        // next-point gathers overlap with loop-back into stage 1
        qf = g_qkv[inds_s[0] * 768 + tt];
        {
            const int j1 = inds_s[tt >> 4];
            sx = s_pts[j1 * 3 + 0];
            sy = s_pts[j1 * 3 + 1];
            sz = s_pts[j1 * 3 + 2];
        }
        #pragma unroll
        for (int h = 0; h < 16; h++)
            nk[h] = g_qkv[inds_s[h] * 768 + 256 + tt];
    }
}

// --------------------------- launch ------------------------------------------
extern "C" void kernel_launch(void* const* d_in, const int* in_sizes, int n_in,
                              void* d_out, int out_size) {
    const float* q_pts   = (const float*)d_in[0];
    const float* s_pts   = (const float*)d_in[1];
    const float* s_feats = (const float*)d_in[2];
    const void*  nb_inds = d_in[3];
    const float* Wq = (const float*)d_in[4];
    const float* bq = (const float*)d_in[5];
    const float* Wk = (const float*)d_in[6];
    const float* bk = (const float*)d_in[7];
    const float* Wv = (const float*)d_in[8];
    const float* bv = (const float*)d_in[9];
    const float* Wd1 = (const float*)d_in[10];
    const float* bd1 = (const float*)d_in[11];
    const float* Wd2 = (const float*)d_in[12];
    const float* bd2 = (const float*)d_in[13];
    const float* Wa1 = (const float*)d_in[14];
    const float* ba1 = (const float*)d_in[15];
    const float* Wa2 = (const float*)d_in[16];
    const float* ba2 = (const float*)d_in[17];
    float* out = (float*)d_out;

    const int N = in_sizes[0] / 3;

    cudaFuncSetAttribute(pt_fused_attn,
                         cudaFuncAttributeMaxDynamicSharedMemorySize, SMEM_BYTES);
    cudaFuncSetAttribute(pt_qkv_gemm_mma,
                         cudaFuncAttributeMaxDynamicSharedMemorySize, GEMM_SMEM);

    pt_prologue<<<MPAD / 4, 256>>>((const unsigned*)nb_inds, N * HH,
                                   s_feats, N,
                                   Wq, bq, Wk, bk, Wv, bv, Wd2, Wa1);

    dim3 ggrid((N + 127) / 128, 6);
    pt_qkv_gemm_mma<<<ggrid, 256, GEMM_SMEM>>>(N);

    int fgrid = 148;
    if (fgrid * 3 > N) fgrid = (N + 2) / 3;
    pt_fused_attn<<<fgrid, 768, SMEM_BYTES>>>(q_pts, s_pts,
                                              Wd1, bd1, bd2,
                                              ba1, Wa2, ba2,
                                              out, N);
}

// round 15
// speedup vs baseline: 1.2618x; 1.0082x over previous
#include <cuda_runtime.h>
#include <cuda_bf16.h>

// ---------------------------------------------------------------------------
// point_transformer, Round 15  (R14 + B3 -> __syncwarp, the isolated safe
//   half of R13: stage2->stage3 is warp-column-local, verified)
// ---------------------------------------------------------------------------
#define NMAX 50000
#define MPAD 50048     // 391 * 128
#define HH   16

typedef unsigned long long ull;

__device__ float g_qkv[NMAX * 768];     // [n][0:256)=q [256:512)=k [512:768)=v
__device__ int   g_inds[NMAX * HH];
__device__ float g_bcat[768];
__device__ __nv_bfloat16 g_ahi[MPAD * 256];
__device__ __nv_bfloat16 g_alo[MPAD * 256];
__device__ __nv_bfloat16 g_whiT[768 * 256];    // Wcat^T: [n][k]
__device__ __nv_bfloat16 g_wloT[768 * 256];
__device__ __nv_bfloat16 g_wd2hiT[256 * 64];   // Wd2^T: [c][d]
__device__ __nv_bfloat16 g_wd2loT[256 * 64];
__device__ __nv_bfloat16 g_wa1hiT[32 * 256];   // Wa1^T: [m][c]
__device__ __nv_bfloat16 g_wa1loT[32 * 256];

static __device__ __forceinline__ float lrelu(float x) {
    return fmaxf(x, 0.1f * x);
}
static __device__ __forceinline__ ull ffma2(ull a, ull b, ull c) {
    ull d;
    asm("fma.rn.f32x2 %0, %1, %2, %3;" : "=l"(d) : "l"(a), "l"(b), "l"(c));
    return d;
}
static __device__ __forceinline__ ull addf2(ull a, ull b) {
    ull d;
    asm("add.rn.f32x2 %0, %1, %2;" : "=l"(d) : "l"(a), "l"(b));
    return d;
}
static __device__ __forceinline__ ull pack2(float x, float y) {
    ull r;
    asm("mov.b64 %0, {%1, %2};" : "=l"(r) : "f"(x), "f"(y));
    return r;
}
static __device__ __forceinline__ float2 unpack2(ull v) {
    float2 f;
    asm("mov.b64 {%0, %1}, %2;" : "=f"(f.x), "=f"(f.y) : "l"(v));
    return f;
}
static __device__ __forceinline__ void mma_bf16(float* d, const unsigned* a,
                                                const unsigned* b) {
    asm volatile(
        "mma.sync.aligned.m16n8k16.row.col.f32.bf16.bf16.f32 "
        "{%0,%1,%2,%3}, {%4,%5,%6,%7}, {%8,%9}, {%0,%1,%2,%3};"
        : "+f"(d[0]), "+f"(d[1]), "+f"(d[2]), "+f"(d[3])
        : "r"(a[0]), "r"(a[1]), "r"(a[2]), "r"(a[3]), "r"(b[0]), "r"(b[1]));
}
static __device__ __forceinline__ ull pack4bf_hi(float a, float b, float c, float d) {
    unsigned short u0 = __bfloat16_as_ushort(__float2bfloat16(a));
    unsigned short u1 = __bfloat16_as_ushort(__float2bfloat16(b));
    unsigned short u2 = __bfloat16_as_ushort(__float2bfloat16(c));
    unsigned short u3 = __bfloat16_as_ushort(__float2bfloat16(d));
    return (ull)u0 | ((ull)u1 << 16) | ((ull)u2 << 32) | ((ull)u3 << 48);
}
static __device__ __forceinline__ unsigned smem_u32(const void* p) {
    unsigned a;
    asm("{ .reg .u64 t; cvta.to.shared.u64 t, %1; cvt.u32.u64 %0, t; }"
        : "=r"(a) : "l"(p));
    return a;
}
static __device__ __forceinline__ void cp16(unsigned smaddr, const void* g) {
    asm volatile("cp.async.cg.shared.global [%0], [%1], 16;"
                 :: "r"(smaddr), "l"(g) : "memory");
}
#define CP_COMMIT() asm volatile("cp.async.commit_group;" ::: "memory")
#define CP_WAIT(n)  asm volatile("cp.async.wait_group %0;" :: "n"(n) : "memory")

// --------------------------- fused prologue (float4-vectorized) -------------
__global__ void pt_prologue(const unsigned* __restrict__ nb, int total_idx,
                            const float* __restrict__ A, int M,
                            const float* __restrict__ Wq, const float* __restrict__ bq,
                            const float* __restrict__ Wk, const float* __restrict__ bk,
                            const float* __restrict__ Wv, const float* __restrict__ bv,
                            const float* __restrict__ Wd2, const float* __restrict__ Wa1) {
    const int b = blockIdx.x;
    const int t = threadIdx.x;
    const int i = b * 256 + t;

    // A -> bf16 hi/lo, 4 elements per thread (grid = MPAD/4 blocks)
    {
        const int i4  = i * 4;
        const int row = i4 >> 8;
        float4 av = (row < M) ? *(const float4*)&A[i4]
                              : make_float4(0.f, 0.f, 0.f, 0.f);
        float h0 = __bfloat162float(__float2bfloat16(av.x));
        float h1 = __bfloat162float(__float2bfloat16(av.y));
        float h2 = __bfloat162float(__float2bfloat16(av.z));
        float h3 = __bfloat162float(__float2bfloat16(av.w));
        *(ull*)&g_ahi[i4] = pack4bf_hi(h0, h1, h2, h3);
        *(ull*)&g_alo[i4] = pack4bf_hi(av.x - h0, av.y - h1, av.z - h2, av.w - h3);
    }
    if (i < 768 * 256) {
        int n = i >> 8, k = i & 255;
        float w;
        if      (n < 256) w = Wq[k * 256 + n];
        else if (n < 512) w = Wk[k * 256 + (n - 256)];
        else              w = Wv[k * 256 + (n - 512)];
        __nv_bfloat16 hi = __float2bfloat16(w);
        g_whiT[i] = hi;
        g_wloT[i] = __float2bfloat16(w - __bfloat162float(hi));
    }
    if (i < 256 * 64) {
        int c = i >> 6, d = i & 63;
        float w = Wd2[d * 256 + c];
        __nv_bfloat16 hi = __float2bfloat16(w);
        g_wd2hiT[i] = hi;
        g_wd2loT[i] = __float2bfloat16(w - __bfloat162float(hi));
    }
    if (i < 32 * 256) {
        int m = i >> 8, k = i & 255;
        float w = Wa1[k * 32 + m];
        __nv_bfloat16 hi = __float2bfloat16(w);
        g_wa1hiT[i] = hi;
        g_wa1loT[i] = __float2bfloat16(w - __bfloat162float(hi));
    }
    if (i < 768) {
        g_bcat[i] = (i < 256) ? bq[i] : (i < 512 ? bk[i - 256] : bv[i - 512]);
    }
    if (b * 256 < total_idx) {
        __shared__ int flag;
        if (t == 0) flag = 0;
        __syncthreads();
        const int half = total_idx >> 1;
        int stride = half >> 8;
        if (stride < 1) stride = 1;
        int s = (t * stride) % half;
        if (nb[2 * s + 1] != 0u) flag = 1;
        __syncthreads();
        if (i < total_idx) {
            if (flag) g_inds[i] = ((const int*)nb)[i];
            else      g_inds[i] = (int)(((const long long*)nb)[i]);
        }
    }
}

// --------------------------- mma.sync QKV GEMM (cp.async x4 stages) ---------
#define SK2     24
#define TILE2   (128 * SK2 * 2)          // 6144 bytes per tile
#define STAGE2  (4 * TILE2)              // 24576: Ahi|Alo|Bhi|Blo
#define NSTAGE  4
#define GEMM_SMEM (NSTAGE * STAGE2)      // 98304

extern __shared__ char sm_raw[];

__global__ void __launch_bounds__(256, 2)
pt_qkv_gemm_mma(int M) {
    char* gsm = sm_raw;
    const unsigned sbase = smem_u32(gsm);

    const int t    = threadIdx.x;
    const int warp = t >> 5;
    const int lane = t & 31;
    const int gid  = lane >> 2;
    const int tq   = lane & 3;
    const int m0 = blockIdx.x * 128;
    const int n0 = blockIdx.y * 128;
    const int mw = (warp & 1) * 64;
    const int nw = (warp >> 1) * 32;

    const int crow = t >> 1;
    const int ckq  = t & 1;

    float acc[4][4][4];
    #pragma unroll
    for (int mt = 0; mt < 4; mt++)
        #pragma unroll
        for (int nt = 0; nt < 4; nt++)
            #pragma unroll
            for (int r = 0; r < 4; r++) acc[mt][nt][r] = 0.f;

    auto issue = [&](int kc, int buf) {
        const int k0 = kc * 16;
        const unsigned dst = sbase + buf * STAGE2 + crow * (SK2 * 2) + ckq * 16;
        const int asrc = (m0 + crow) * 256 + k0 + ckq * 8;
        const int bsrc = (n0 + crow) * 256 + k0 + ckq * 8;
        cp16(dst + 0 * TILE2, &g_ahi[asrc]);
        cp16(dst + 1 * TILE2, &g_alo[asrc]);
        cp16(dst + 2 * TILE2, &g_whiT[bsrc]);
        cp16(dst + 3 * TILE2, &g_wloT[bsrc]);
        CP_COMMIT();
    };

    issue(0, 0);
    issue(1, 1);
    issue(2, 2);

    for (int kc = 0; kc < 16; kc++) {
        CP_WAIT(2);
        __syncthreads();

        char* base = gsm + (kc & 3) * STAGE2;
        const __nv_bfloat16* smAhi = (const __nv_bfloat16*)(base);
        const __nv_bfloat16* smAlo = (const __nv_bfloat16*)(base + 1 * TILE2);
        const __nv_bfloat16* smBhi = (const __nv_bfloat16*)(base + 2 * TILE2);
        const __nv_bfloat16* smBlo = (const __nv_bfloat16*)(base + 3 * TILE2);

        const int kk = tq * 2;
        unsigned bh[4][2], bl[4][2];
        #pragma unroll
        for (int nt = 0; nt < 4; nt++) {
            const int nr = nw + nt * 8 + gid;
            bh[nt][0] = *(const unsigned*)&smBhi[nr * SK2 + kk];
            bh[nt][1] = *(const unsigned*)&smBhi[nr * SK2 + kk + 8];
            bl[nt][0] = *(const unsigned*)&smBlo[nr * SK2 + kk];
            bl[nt][1] = *(const unsigned*)&smBlo[nr * SK2 + kk + 8];
        }
        #pragma unroll
        for (int mt = 0; mt < 4; mt++) {
            const int mr = mw + mt * 16 + gid;
            unsigned ah[4], al[4];
            ah[0] = *(const unsigned*)&smAhi[ mr      * SK2 + kk];
            ah[1] = *(const unsigned*)&smAhi[(mr + 8) * SK2 + kk];
            ah[2] = *(const unsigned*)&smAhi[ mr      * SK2 + kk + 8];
            ah[3] = *(const unsigned*)&smAhi[(mr + 8) * SK2 + kk + 8];
            al[0] = *(const unsigned*)&smAlo[ mr      * SK2 + kk];
            al[1] = *(const unsigned*)&smAlo[(mr + 8) * SK2 + kk];
            al[2] = *(const unsigned*)&smAlo[ mr      * SK2 + kk + 8];
            al[3] = *(const unsigned*)&smAlo[(mr + 8) * SK2 + kk + 8];
            #pragma unroll
            for (int nt = 0; nt < 4; nt++) {
                mma_bf16(acc[mt][nt], ah, bh[nt]);
                mma_bf16(acc[mt][nt], ah, bl[nt]);
                mma_bf16(acc[mt][nt], al, bh[nt]);
            }
        }

        if (kc + 3 < 16) issue(kc + 3, (kc + 3) & 3);
    }

    #pragma unroll
    for (int mt = 0; mt < 4; mt++) {
        const int r0 = m0 + mw + mt * 16 + gid;
        const int r1 = r0 + 8;
        #pragma unroll
        for (int nt = 0; nt < 4; nt++) {
            const int col = n0 + nw + nt * 8 + tq * 2;
            const float b0 = g_bcat[col], b1 = g_bcat[col + 1];
            if (r0 < M) {
                float2 o = make_float2(acc[mt][nt][0] + b0, acc[mt][nt][1] + b1);
                *(float2*)&g_qkv[r0 * 768 + col] = o;
            }
            if (r1 < M) {
                float2 o = make_float2(acc[mt][nt][2] + b0, acc[mt][nt][3] + b1);
                *(float2*)&g_qkv[r1 * 768 + col] = o;
            }
        }
    }
}

// --------------------------- fused attention --------------------------------
// 768 threads = three independent 256-thread halves (named barriers 1/2/3).
// h-pair convention: pair hp = (h=hp, h=hp+8). Cross-point software pipeline.
// Stage 2 -> stage 3 is warp-column-local: __syncwarp instead of barrier.
#define OFF_WD2H  0        // bf16 [256][72] -> 9216 floats
#define OFF_WD2L  9216
#define OFF_WA1L  18432    // bf16 [32][264] -> 4224 floats
#define OFF_WA2   22656    // [32][32]
#define OFF_WD1   23680
#define OFF_BD1   23872
#define OFF_BD2   23936
#define OFF_BA1   24192
#define OFF_BA2   24224
#define WEIGHT_FLOATS 24256

#define PP_AH     0        // bf16 [16][264] = 2112 floats
#define PP_AL     2112     // bf16 [16][264]
#define PP_GP     4224     // OVERLAY: geom2 ull[8][260] (4160) / partu ull[8][8][34] (4352)
#define PP_L1     8576     // [16][34]
#define PP_L2     9120     // [16][34]
#define PP_ATTN   9664     // ull [8][34] = 544 floats
#define PP_INDS   10208    // 16 ints
#define PP_QPT    10224    // 3 floats + pad
#define PP_FLOATS 10228

#define SMEM_FLOATS (WEIGHT_FLOATS + 3 * PP_FLOATS)
#define SMEM_BYTES  (SMEM_FLOATS * 4)

#define HBAR(id) asm volatile("bar.sync %0, 256;" :: "r"(id) : "memory")

__global__ void __launch_bounds__(768, 1)
pt_fused_attn(const float* __restrict__ q_pts,
              const float* __restrict__ s_pts,
              const float* __restrict__ Wd1, const float* __restrict__ bd1,
              const float* __restrict__ bd2,
              const float* __restrict__ ba1,
              const float* __restrict__ Wa2, const float* __restrict__ ba2,
              float* __restrict__ out, int N) {
    float* sm = (float*)sm_raw;
    __nv_bfloat16* Wd2THs = (__nv_bfloat16*)(sm + OFF_WD2H);  // [256 c][72 d]
    __nv_bfloat16* Wd2TLs = (__nv_bfloat16*)(sm + OFF_WD2L);
    __nv_bfloat16* Wa1Ls  = (__nv_bfloat16*)(sm + OFF_WA1L);  // [32 m][264 c]
    float* Wa2s = sm + OFF_WA2;
    float* Wd1s = sm + OFF_WD1;
    float* bd1s = sm + OFF_BD1;
    float* bd2s = sm + OFF_BD2;
    float* ba1s = sm + OFF_BA1;
    float* ba2s = sm + OFF_BA2;

    const int t   = threadIdx.x;
    const int pid = t >> 8;         // 0,1,2
    const int tt  = t & 255;
    const int ww  = (t >> 5) & 7;   // warp in half: owns c-slice [32ww, 32ww+32)
    const int l   = t & 31;
    const int gid = l >> 2;
    const int tq  = l & 3;
    const int bid = pid + 1;

    float* pp     = sm + WEIGHT_FLOATS + pid * PP_FLOATS;
    __nv_bfloat16* aH = (__nv_bfloat16*)(pp + PP_AH);   // [16 h][264 c]
    __nv_bfloat16* aL = (__nv_bfloat16*)(pp + PP_AL);
    ull*   geom2  = (ull*)(pp + PP_GP);     // [8 hp][260 c]   (overlay)
    ull*   partu  = (ull*)(pp + PP_GP);     // [(ww*8+hp)*34+m] (overlay)
    float* l1s    = pp + PP_L1;
    float* l2s    = pp + PP_L2;
    ull*   attn2  = (ull*)(pp + PP_ATTN);
    int*   inds_s = (int*)(pp + PP_INDS);
    float* qptf   = pp + PP_QPT;

    // persistent Wa1 HI B-fragments in registers; LO stays in smem
    unsigned wbh[4][2][2];
    #pragma unroll
    for (int nt = 0; nt < 4; nt++)
        #pragma unroll
        for (int s = 0; s < 2; s++) {
            const int m  = nt * 8 + gid;
            const int k0 = ww * 32 + s * 16 + tq * 2;
            wbh[nt][s][0] = *(const unsigned*)&g_wa1hiT[m * 256 + k0];
            wbh[nt][s][1] = *(const unsigned*)&g_wa1hiT[m * 256 + k0 + 8];
        }

    // stage 0: weights -> shared (all 768 threads)
    for (int i = t; i < 256 * 16; i += 768) {
        int n = i >> 4, k4 = (i & 15) * 4;
        *(ull*)&Wd2THs[n * 72 + k4] = ((const ull*)g_wd2hiT)[i];
        *(ull*)&Wd2TLs[n * 72 + k4] = ((const ull*)g_wd2loT)[i];
    }
    for (int i = t; i < 2048; i += 768) {
        int m = i >> 6, u = i & 63;
        *(ull*)&Wa1Ls[m * 264 + u * 4] = ((const ull*)g_wa1loT)[i];
    }
    for (int i = t; i < 1024; i += 768) Wa2s[i] = Wa2[i];
    if (t < 192) Wd1s[t] = Wd1[t];
    if (t < 64)  bd1s[t] = bd1[t];
    if (t < 256) bd2s[t] = bd2[t];
    if (t < 32) { ba1s[t] = ba1[t]; ba2s[t] = ba2[t]; }
    __syncthreads();

    // ---- pipeline preamble: first point's indices + gather prefetch ----
    int n3 = blockIdx.x;
    {
        int nreq = n3 * 3 + pid;
        int n0p  = (nreq < N) ? nreq : (N - 1);
        if (tt < 16) inds_s[tt] = g_inds[n0p * 16 + tt];
        if (tt < 3)  qptf[tt]   = q_pts[n0p * 3 + tt];
    }
    HBAR(bid);

    float qf, sx, sy, sz, nk[16];
    qf = g_qkv[inds_s[0] * 768 + tt];
    {
        const int j1 = inds_s[tt >> 4];
        sx = s_pts[j1 * 3 + 0];
        sy = s_pts[j1 * 3 + 1];
        sz = s_pts[j1 * 3 + 2];
    }
    #pragma unroll
    for (int h = 0; h < 16; h++)
        nk[h] = g_qkv[inds_s[h] * 768 + 256 + tt];

    while (true) {
        const int nreq = n3 * 3 + pid;
        const int n = (nreq < N) ? nreq : (N - 1);
        const bool do_store = (nreq < N);

        // stage 1: hidden = lrelu(rel @ Wd1 + bd1), bf16 hi/lo (stride 72)
        {
            const int d0 = (tt & 15) << 2;
            const int h  = tt >> 4;
            const float rx = sx - qptf[0];
            const float ry = sy - qptf[1];
            const float rz = sz - qptf[2];
            float vv[4], vh[4], vl[4];
            #pragma unroll
            for (int i = 0; i < 4; i++) {
                const int d = d0 + i;
                float v = rx * Wd1s[d] + ry * Wd1s[64 + d] + rz * Wd1s[128 + d] + bd1s[d];
                vv[i] = lrelu(v);
                vh[i] = __bfloat162float(__float2bfloat16(vv[i]));
                vl[i] = vv[i] - vh[i];
            }
            *(ull*)&aH[h * 72 + d0] = pack4bf_hi(vh[0], vh[1], vh[2], vh[3]);
            *(ull*)&aL[h * 72 + d0] = pack4bf_hi(vl[0], vl[1], vl[2], vl[3]);
        }
        HBAR(bid);                                          // B2

        // stage 2: geom = hid @ Wd2 via mma (hi/lo split); D rows (gid, gid+8)
        {
            float acc[4][4];
            #pragma unroll
            for (int nt = 0; nt < 4; nt++)
                #pragma unroll
                for (int r = 0; r < 4; r++) acc[nt][r] = 0.f;

            #pragma unroll
            for (int kc = 0; kc < 4; kc++) {
                const int k0 = kc * 16;
                unsigned ah[4], al[4];
                ah[0] = *(const unsigned*)&aH[ gid      * 72 + k0 + tq * 2];
                ah[1] = *(const unsigned*)&aH[(gid + 8) * 72 + k0 + tq * 2];
                ah[2] = *(const unsigned*)&aH[ gid      * 72 + k0 + 8 + tq * 2];
                ah[3] = *(const unsigned*)&aH[(gid + 8) * 72 + k0 + 8 + tq * 2];
                al[0] = *(const unsigned*)&aL[ gid      * 72 + k0 + tq * 2];
                al[1] = *(const unsigned*)&aL[(gid + 8) * 72 + k0 + tq * 2];
                al[2] = *(const unsigned*)&aL[ gid      * 72 + k0 + 8 + tq * 2];
                al[3] = *(const unsigned*)&aL[(gid + 8) * 72 + k0 + 8 + tq * 2];
                #pragma unroll
                for (int nt = 0; nt < 4; nt++) {
                    const int nr = ww * 32 + nt * 8 + gid;
                    unsigned bh[2], bl[2];
                    bh[0] = *(const unsigned*)&Wd2THs[nr * 72 + k0 + tq * 2];
                    bh[1] = *(const unsigned*)&Wd2THs[nr * 72 + k0 + 8 + tq * 2];
                    bl[0] = *(const unsigned*)&Wd2TLs[nr * 72 + k0 + tq * 2];
                    bl[1] = *(const unsigned*)&Wd2TLs[nr * 72 + k0 + 8 + tq * 2];
                    mma_bf16(acc[nt], ah, bh);
                    mma_bf16(acc[nt], ah, bl);
                    mma_bf16(acc[nt], al, bh);
                }
            }
            #pragma unroll
            for (int nt = 0; nt < 4; nt++) {
                const int c0 = ww * 32 + nt * 8 + tq * 2;
                const float b0 = bd2s[c0], b1 = bd2s[c0 + 1];
                geom2[gid * 260 + c0    ] = pack2(acc[nt][0] + b0, acc[nt][2] + b0);
                geom2[gid * 260 + c0 + 1] = pack2(acc[nt][1] + b1, acc[nt][3] + b1);
            }
        }
        __syncwarp();   // stage 2 -> 3 warp-local (geom2 columns == warp slice)

        // stage 3: a = lrelu(qf - nk - geom); store bf16 hi/lo [16][264]
        ull g[8];
        #pragma unroll
        for (int hp = 0; hp < 8; hp++) {
            g[hp] = geom2[hp * 260 + tt];
            const float2 gp = unpack2(g[hp]);
            const float ax = lrelu(qf - nk[hp]     - gp.x);
            const float ay = lrelu(qf - nk[hp + 8] - gp.y);
            __nv_bfloat16 hx = __float2bfloat16(ax);
            __nv_bfloat16 hy = __float2bfloat16(ay);
            aH[ hp      * 264 + tt] = hx;
            aH[(hp + 8) * 264 + tt] = hy;
            aL[ hp      * 264 + tt] = __float2bfloat16(ax - __bfloat162float(hx));
            aL[(hp + 8) * 264 + tt] = __float2bfloat16(ay - __bfloat162float(hy));
        }
        HBAR(bid);      // B4: all geom2 reads done before partu overlay writes

        // stage 4: logits1 partials via mma (Wa1 hi in regs, lo in smem)
        {
            float acc[4][4];
            #pragma unroll
            for (int nt = 0; nt < 4; nt++)
                #pragma unroll
                for (int r = 0; r < 4; r++) acc[nt][r] = 0.f;

            #pragma unroll
            for (int s = 0; s < 2; s++) {
                const int kk = ww * 32 + s * 16 + tq * 2;
                unsigned ah[4], al[4];
                ah[0] = *(const unsigned*)&aH[ gid      * 264 + kk];
                ah[1] = *(const unsigned*)&aH[(gid + 8) * 264 + kk];
                ah[2] = *(const unsigned*)&aH[ gid      * 264 + kk + 8];
                ah[3] = *(const unsigned*)&aH[(gid + 8) * 264 + kk + 8];
                al[0] = *(const unsigned*)&aL[ gid      * 264 + kk];
                al[1] = *(const unsigned*)&aL[(gid + 8) * 264 + kk];
                al[2] = *(const unsigned*)&aL[ gid      * 264 + kk + 8];
                al[3] = *(const unsigned*)&aL[(gid + 8) * 264 + kk + 8];
                #pragma unroll
                for (int nt = 0; nt < 4; nt++) {
                    const int m = nt * 8 + gid;
                    unsigned bl[2];
                    bl[0] = *(const unsigned*)&Wa1Ls[m * 264 + ww * 32 + s * 16 + tq * 2];
                    bl[1] = *(const unsigned*)&Wa1Ls[m * 264 + ww * 32 + s * 16 + tq * 2 + 8];
                    mma_bf16(acc[nt], ah, wbh[nt][s]);
                    mma_bf16(acc[nt], ah, bl);
                    mma_bf16(acc[nt], al, wbh[nt][s]);
                }
            }
            #pragma unroll
            for (int nt = 0; nt < 4; nt++) {
                const int m = nt * 8 + tq * 2;
                ulonglong2 v;
                v.x = pack2(acc[nt][0], acc[nt][2]);
                v.y = pack2(acc[nt][1], acc[nt][3]);
                *(ulonglong2*)&partu[(ww * 8 + gid) * 34 + m] = v;
            }
        }

        // early LDGs: next point's indices/qpt into REGISTERS (pre-B5:
        // latency hidden under stage-4 MMAs) + current point's nv prefetch
        const int n3n = n3 + gridDim.x;
        int   nxt_ind = 0;
        float nxt_qp  = 0.f;
        {
            int nreqn = n3n * 3 + pid;
            int nn = (nreqn < N) ? nreqn : (N - 1);
            if (tt < 16) nxt_ind = g_inds[nn * 16 + tt];
            if (tt < 3)  nxt_qp  = q_pts[nn * 3 + tt];
        }
        float nv[16];
        #pragma unroll
        for (int h = 0; h < 16; h++)
            nv[h] = g_qkv[inds_s[h] * 768 + 512 + tt];
        HBAR(bid);                                          // B5

        // commit pipeline advance (inds_s free after B5)
        n3 = n3n;
        const bool more = (n3 * 3 < N);    // uniform across CTA
        if (tt < 16) inds_s[tt] = nxt_ind;
        if (tt < 3)  qptf[tt]   = nxt_qp;

        // stage 4b+5 merged (warp-local): warp w reduces l1 rows (w, w+8),
        // then computes l2 rows after __syncwarp.
        {
            const float b = ba1s[l];
            ull s = pack2(b, b);
            #pragma unroll
            for (int w8 = 0; w8 < 8; w8++)
                s = addf2(s, partu[(w8 * 8 + ww) * 34 + l]);
            float2 v = unpack2(s);
            l1s[ ww      * 34 + l] = lrelu(v.x);
            l1s[(ww + 8) * 34 + l] = lrelu(v.y);
            __syncwarp();

            const int h  = ww + 8 * (l >> 4);
            const int m0 = (l & 15) * 2;
            ull acc01 = pack2(ba2s[m0], ba2s[m0 + 1]);
            const float* lrow = l1s + h * 34;
            #pragma unroll
            for (int jj = 0; jj < 32; jj++) {
                const float lv = lrow[jj];
                ull w2 = *(const ull*)(Wa2s + jj * 32 + m0);
                acc01 = ffma2(pack2(lv, lv), w2, acc01);
            }
            float2 r = unpack2(acc01);
            l2s[h * 34 + m0    ] = r.x;
            l2s[h * 34 + m0 + 1] = r.y;
        }
        HBAR(bid);                                          // B6

        // stage 6: softmax over h; attn pairs (hp, hp+8)
        if (tt < 32) {
            float vals[16];
            float mx = -3.4e38f;
            #pragma unroll
            for (int h = 0; h < 16; h++) {
                vals[h] = l2s[h * 34 + tt];
                mx = fmaxf(mx, vals[h]);
            }
            float s = 0.f;
            #pragma unroll
            for (int h = 0; h < 16; h++) {
                vals[h] = __expf(vals[h] - mx);
                s += vals[h];
            }
            const float inv = 1.f / s;
            #pragma unroll
            for (int hp = 0; hp < 8; hp++)
                attn2[hp * 34 + tt] = pack2(vals[hp] * inv, vals[hp + 8] * inv);
        }
        HBAR(bid);                                          // B7

        // stage 7: out + NEXT point's gather prefetch (new inds_s visible)
        {
            const int mg = tt >> 3;
            ull acc2p = 0ull;
            #pragma unroll
            for (int hp = 0; hp < 8; hp++) {
                const float2 gp = unpack2(g[hp]);
                ull vm = pack2(nv[hp] - gp.x, nv[hp + 8] - gp.y);
                acc2p = ffma2(vm, attn2[hp * 34 + mg], acc2p);
            }
            float2 r = unpack2(acc2p);
            if (do_store) out[n * 256 + tt] = r.x + r.y;
        }
        if (!more) break;

        // next-point gathers overlap with loop-back into stage 1
        qf = g_qkv[inds_s[0] * 768 + tt];
        {
            const int j1 = inds_s[tt >> 4];
            sx = s_pts[j1 * 3 + 0];
            sy = s_pts[j1 * 3 + 1];
            sz = s_pts[j1 * 3 + 2];
        }
        #pragma unroll
        for (int h = 0; h < 16; h++)
            nk[h] = g_qkv[inds_s[h] * 768 + 256 + tt];
    }
}

// --------------------------- launch ------------------------------------------
extern "C" void kernel_launch(void* const* d_in, const int* in_sizes, int n_in,
                              void* d_out, int out_size) {
    const float* q_pts   = (const float*)d_in[0];
    const float* s_pts   = (const float*)d_in[1];
    const float* s_feats = (const float*)d_in[2];
    const void*  nb_inds = d_in[3];
    const float* Wq = (const float*)d_in[4];
    const float* bq = (const float*)d_in[5];
    const float* Wk = (const float*)d_in[6];
    const float* bk = (const float*)d_in[7];
    const float* Wv = (const float*)d_in[8];
    const float* bv = (const float*)d_in[9];
    const float* Wd1 = (const float*)d_in[10];
    const float* bd1 = (const float*)d_in[11];
    const float* Wd2 = (const float*)d_in[12];
    const float* bd2 = (const float*)d_in[13];
    const float* Wa1 = (const float*)d_in[14];
    const float* ba1 = (const float*)d_in[15];
    const float* Wa2 = (const float*)d_in[16];
    const float* ba2 = (const float*)d_in[17];
    float* out = (float*)d_out;

    const int N = in_sizes[0] / 3;

    cudaFuncSetAttribute(pt_fused_attn,
                         cudaFuncAttributeMaxDynamicSharedMemorySize, SMEM_BYTES);
    cudaFuncSetAttribute(pt_qkv_gemm_mma,
                         cudaFuncAttributeMaxDynamicSharedMemorySize, GEMM_SMEM);

    pt_prologue<<<MPAD / 4, 256>>>((const unsigned*)nb_inds, N * HH,
                                   s_feats, N,
                                   Wq, bq, Wk, bk, Wv, bv, Wd2, Wa1);

    dim3 ggrid((N + 127) / 128, 6);
    pt_qkv_gemm_mma<<<ggrid, 256, GEMM_SMEM>>>(N);

    int fgrid = 148;
    if (fgrid * 3 > N) fgrid = (N + 2) / 3;
    pt_fused_attn<<<fgrid, 768, SMEM_BYTES>>>(q_pts, s_pts,
                                              Wd1, bd1, bd2,
                                              ba1, Wa2, ba2,
                                              out, N);
}